// round 5
// baseline (speedup 1.0000x reference)
#include <cuda_runtime.h>
#include <cstdint>

// ---------------------------------------------------------------------------
// DoseEncoder: out[t] = sum_d MLP(feats(t,d)) * mask * exp(-0.5*(dt/sigma)^2)
//
// Design:
//  * h1_pre = U[t] + V[d]  (algebraic split of layer 1)
//  * 2 doses packed per thread into f32x2; all GEMV FMAs are fma.rn.f32x2
//  * weights duplicated {w,w} in SMEM -> one LDS.128 broadcast = 2 packed weights
//  * block of 128 threads = 256 doses of one t; loops over 16 t per block
//  * SiLU = x * rcp(1 + ex2(-x*log2e))   (ex2.approx + rcp.approx)
// ---------------------------------------------------------------------------

#define TPB   128
#define G_T   16
#define HID   32

struct __align__(16) Smem {
    float2 V2[HID * TPB];    // [i][dose-pack]  (pack p holds doses 2p, 2p+1)
    float2 W2d[HID * HID];   // [j][i], duplicated {w,w}
    float2 W3d[HID * HID];
    float2 W4d[HID];
    float2 B2d[HID];
    float2 B3d[HID];
    float2 U[HID];           // {u,u} per hidden unit, rebuilt per t
    float  redMin[4];
    float  redSum[4];
};

// ---- packed f32x2 helpers --------------------------------------------------
__device__ __forceinline__ unsigned long long f2u(float2 v) {
    union { float2 f; unsigned long long u; } x; x.f = v; return x.u;
}
__device__ __forceinline__ float2 u2f(unsigned long long u) {
    union { float2 f; unsigned long long u; } x; x.u = u; return x.f;
}
__device__ __forceinline__ float2 fma2(float2 a, float2 b, float2 c) {
    unsigned long long r;
    asm("fma.rn.f32x2 %0, %1, %2, %3;" : "=l"(r) : "l"(f2u(a)), "l"(f2u(b)), "l"(f2u(c)));
    return u2f(r);
}
__device__ __forceinline__ float2 add2(float2 a, float2 b) {
    unsigned long long r;
    asm("add.rn.f32x2 %0, %1, %2;" : "=l"(r) : "l"(f2u(a)), "l"(f2u(b)));
    return u2f(r);
}
__device__ __forceinline__ float2 mul2(float2 a, float2 b) {
    unsigned long long r;
    asm("mul.rn.f32x2 %0, %1, %2;" : "=l"(r) : "l"(f2u(a)), "l"(f2u(b)));
    return u2f(r);
}
__device__ __forceinline__ float ex2f(float x) {
    float r; asm("ex2.approx.f32 %0, %1;" : "=f"(r) : "f"(x)); return r;
}
__device__ __forceinline__ float rcpf_(float x) {
    float r; asm("rcp.approx.f32 %0, %1;" : "=f"(r) : "f"(x)); return r;
}

// silu(x) = x / (1 + exp(-x)), elementwise on both packed lanes
__device__ __forceinline__ float2 silu2(float2 x) {
    const float NL2E = -1.4426950408889634f;
    float2 t = mul2(x, make_float2(NL2E, NL2E));
    float e0 = ex2f(t.x);
    float e1 = ex2f(t.y);
    float2 den = add2(make_float2(e0, e1), make_float2(1.0f, 1.0f));
    float2 r = make_float2(rcpf_(den.x), rcpf_(den.y));
    return mul2(x, r);
}

// One 32->32 layer with SiLU. Wd is [j][i] duplicated weights in SMEM.
__device__ __forceinline__ void layer32(const float2* __restrict__ Wd,
                                        const float2* __restrict__ Bd,
                                        const float2* __restrict__ hin,
                                        float2* __restrict__ hout) {
#pragma unroll
    for (int j = 0; j < HID; j += 4) {
        float2 a0 = Bd[j + 0];
        float2 a1 = Bd[j + 1];
        float2 a2 = Bd[j + 2];
        float2 a3 = Bd[j + 3];
#pragma unroll
        for (int i = 0; i < HID; i += 2) {
            float4 wa = *reinterpret_cast<const float4*>(Wd + (j + 0) * HID + i);
            float4 wb = *reinterpret_cast<const float4*>(Wd + (j + 1) * HID + i);
            float4 wc = *reinterpret_cast<const float4*>(Wd + (j + 2) * HID + i);
            float4 wd = *reinterpret_cast<const float4*>(Wd + (j + 3) * HID + i);
            float2 h0 = hin[i], h1 = hin[i + 1];
            a0 = fma2(h0, make_float2(wa.x, wa.y), a0);
            a0 = fma2(h1, make_float2(wa.z, wa.w), a0);
            a1 = fma2(h0, make_float2(wb.x, wb.y), a1);
            a1 = fma2(h1, make_float2(wb.z, wb.w), a1);
            a2 = fma2(h0, make_float2(wc.x, wc.y), a2);
            a2 = fma2(h1, make_float2(wc.z, wc.w), a2);
            a3 = fma2(h0, make_float2(wd.x, wd.y), a3);
            a3 = fma2(h1, make_float2(wd.z, wd.w), a3);
        }
        hout[j + 0] = silu2(a0);
        hout[j + 1] = silu2(a1);
        hout[j + 2] = silu2(a2);
        hout[j + 3] = silu2(a3);
    }
}

__global__ void __launch_bounds__(TPB, 2)
dose_encoder_kernel(const float* __restrict__ t_abs,
                    const float* __restrict__ dose_t,
                    const float* __restrict__ amts,
                    const float* __restrict__ ss,
                    const float* __restrict__ ii,
                    const float* __restrict__ span_p,
                    const float* __restrict__ logsig,
                    const float* __restrict__ W1,
                    const float* __restrict__ b1,
                    const float* __restrict__ W2,
                    const float* __restrict__ b2,
                    const float* __restrict__ W3,
                    const float* __restrict__ b3,
                    const float* __restrict__ W4,
                    const float* __restrict__ b4,
                    float* __restrict__ out,
                    int T) {
    extern __shared__ char smem_raw[];
    Smem& S = *reinterpret_cast<Smem*>(smem_raw);
    const int tid = threadIdx.x;
    const int lane = tid & 31;
    const int warp = tid >> 5;

    const float span  = span_p[0];
    const float sigma = expf(logsig[0]);
    const float wc_l2 = -0.5f / (sigma * sigma) * 1.4426950408889634f;

    // ---- block prolog: stage duplicated weights ----
    for (int idx = tid; idx < HID * HID; idx += TPB) {
        int i = idx & (HID - 1), j = idx >> 5;
        float w2 = W2[i * HID + j]; S.W2d[j * HID + i] = make_float2(w2, w2);
        float w3 = W3[i * HID + j]; S.W3d[j * HID + i] = make_float2(w3, w3);
    }
    if (tid < HID) {
        float v;
        v = b2[tid]; S.B2d[tid] = make_float2(v, v);
        v = b3[tid]; S.B3d[tid] = make_float2(v, v);
        v = W4[tid]; S.W4d[tid] = make_float2(v, v);
    }

    // ---- per-thread dose pair constants + V vectors ----
    const int d0 = 2 * tid, d1 = 2 * tid + 1;
    const float dn0 = dose_t[d0] / span;
    const float dn1 = dose_t[d1] / span;
    {
        float la0 = log1pf(amts[d0]), la1 = log1pf(amts[d1]);
        float spe = span + 1e-6f;
        float ssn0 = ss[d0] / spe, ssn1 = ss[d1] / spe;
        float iin0 = ii[d0] / spe, iin1 = ii[d1] / spe;
        for (int i = 0; i < HID; i++) {
            float wdt = W1[i];
            float wla = W1[HID + i];
            float wss = W1[3 * HID + i];
            float wii = W1[4 * HID + i];
            float bb  = b1[i];
            float v0 = fmaf(-dn0, wdt, fmaf(la0, wla, fmaf(ssn0, wss, fmaf(iin0, wii, bb))));
            float v1 = fmaf(-dn1, wdt, fmaf(la1, wla, fmaf(ssn1, wss, fmaf(iin1, wii, bb))));
            S.V2[i * TPB + tid] = make_float2(v0, v1);
        }
    }
    __syncthreads();

    const float INFP = __int_as_float(0x7f800000);
    const float b4v  = b4[0];

    const int t0 = blockIdx.x * G_T;
    for (int g = 0; g < G_T; g++) {
        int tt = t0 + g;
        if (tt >= T) break;
        float tnorm = t_abs[tt] / span;
        float dt0 = tnorm - dn0;
        float dt1 = tnorm - dn1;

        // dt_last = min over valid doses (block-wide)
        float m = fminf(dt0 >= 0.0f ? dt0 : INFP, dt1 >= 0.0f ? dt1 : INFP);
#pragma unroll
        for (int off = 16; off > 0; off >>= 1)
            m = fminf(m, __shfl_xor_sync(0xffffffffu, m, off));
        if (lane == 0) S.redMin[warp] = m;
        __syncthreads();
        float dtlast = fminf(fminf(S.redMin[0], S.redMin[1]),
                             fminf(S.redMin[2], S.redMin[3]));
        if (tid < HID) {
            float u = fmaf(tnorm, W1[tid], dtlast * W1[2 * HID + tid]);
            S.U[tid] = make_float2(u, u);
        }
        __syncthreads();

        // ---- layer 1 (adds only) + SiLU ----
        float2 h[HID], hb[HID];
#pragma unroll
        for (int i = 0; i < HID; i++) {
            float2 pre = add2(S.U[i], S.V2[i * TPB + tid]);
            h[i] = silu2(pre);
        }

        // ---- layers 2, 3 ----
        layer32(S.W2d, S.B2d, h, hb);
        layer32(S.W3d, S.B3d, hb, h);

        // ---- layer 4 (dot with W4) ----
        float2 acc = make_float2(b4v, b4v);
#pragma unroll
        for (int i = 0; i < HID; i += 2) {
            float4 w = *reinterpret_cast<const float4*>(S.W4d + i);
            acc = fma2(h[i],     make_float2(w.x, w.y), acc);
            acc = fma2(h[i + 1], make_float2(w.z, w.w), acc);
        }

        // ---- gaussian weight + masked accumulate ----
        float w0  = (dt0 >= 0.0f) ? ex2f(wc_l2 * dt0 * dt0) : 0.0f;
        float w1v = (dt1 >= 0.0f) ? ex2f(wc_l2 * dt1 * dt1) : 0.0f;
        float part = acc.x * w0 + acc.y * w1v;
#pragma unroll
        for (int off = 16; off > 0; off >>= 1)
            part += __shfl_xor_sync(0xffffffffu, part, off);
        if (lane == 0) S.redSum[warp] = part;
        __syncthreads();
        if (tid == 0)
            out[tt] = (S.redSum[0] + S.redSum[1]) + (S.redSum[2] + S.redSum[3]);
    }
}

extern "C" void kernel_launch(void* const* d_in, const int* in_sizes, int n_in,
                              void* d_out, int out_size) {
    const float* t_abs  = (const float*)d_in[0];
    const float* dose_t = (const float*)d_in[1];
    const float* amts   = (const float*)d_in[2];
    const float* ss     = (const float*)d_in[3];
    const float* ii     = (const float*)d_in[4];
    const float* span_p = (const float*)d_in[5];
    const float* logsig = (const float*)d_in[6];
    const float* W1     = (const float*)d_in[7];
    const float* b1     = (const float*)d_in[8];
    const float* W2     = (const float*)d_in[9];
    const float* b2     = (const float*)d_in[10];
    const float* W3     = (const float*)d_in[11];
    const float* b3     = (const float*)d_in[12];
    const float* W4     = (const float*)d_in[13];
    const float* b4     = (const float*)d_in[14];
    float* out = (float*)d_out;
    const int T = in_sizes[0];

    cudaFuncSetAttribute(dose_encoder_kernel,
                         cudaFuncAttributeMaxDynamicSharedMemorySize,
                         (int)sizeof(Smem));

    int grid = (T + G_T - 1) / G_T;
    dose_encoder_kernel<<<grid, TPB, sizeof(Smem)>>>(
        t_abs, dose_t, amts, ss, ii, span_p, logsig,
        W1, b1, W2, b2, W3, b3, W4, b4, out, T);
}

// round 8
// speedup vs baseline: 1.0063x; 1.0063x over previous
#include <cuda_runtime.h>
#include <cstdint>

// ---------------------------------------------------------------------------
// DoseEncoder — j-packed f32x2 formulation.
//
//  * f32x2 lanes = (hidden j, hidden j+1) of ONE dose; 2 doses per thread.
//  * Weight operand {w[i][j], w[i][j+1]} is contiguous row-major -> loaded
//    non-duplicated via ld.shared.v2.u64 (16B -> 4 FFMA2 across both doses).
//  * Activation dup {h_i,h_i} built once per i (1 MOV), reused 32x.
//  * h1_pre = U[t] + V[d] layer-1 split; SiLU via ex2.approx + rcp.approx.
//  * block = 128 threads = 256 doses of one t; 16 t per block.
// ---------------------------------------------------------------------------

#define TPB 128
#define G_T 16

typedef unsigned long long ull;

struct __align__(16) Smem {
    float4 V4[16][TPB];   // [jp][tid] = {vA_2jp, vA_2jp+1, vB_2jp, vB_2jp+1}  (32 KB)
    float  W2s[32 * 32];  // row-major [i][j]   (4 KB)
    float  W3s[32 * 32];  // (4 KB)
    float2 B2p[16];
    float2 B3p[16];
    float2 W4p[16];
    float2 Up[16];        // {u_2j, u_2j+1}, rebuilt per t
    float  W1t[32];       // W1 row for tnorm feature
    float  W1dl[32];      // W1 row for dt_last feature
    float  redMin[4];
    float  redSum[4];
};

// ---- packed f32x2 helpers --------------------------------------------------
__device__ __forceinline__ ull packf2(float a, float b) {
    ull r; asm("mov.b64 %0, {%1, %2};" : "=l"(r) : "f"(a), "f"(b)); return r;
}
__device__ __forceinline__ void unpackf2(ull x, float& a, float& b) {
    asm("mov.b64 {%0, %1}, %2;" : "=f"(a), "=f"(b) : "l"(x));
}
__device__ __forceinline__ ull dupf(float a) {
    ull r; asm("mov.b64 %0, {%1, %1};" : "=l"(r) : "f"(a)); return r;
}
__device__ __forceinline__ ull fma2u(ull a, ull b, ull c) {
    ull r; asm("fma.rn.f32x2 %0, %1, %2, %3;" : "=l"(r) : "l"(a), "l"(b), "l"(c));
    return r;
}
__device__ __forceinline__ float ex2f(float x) {
    float r; asm("ex2.approx.f32 %0, %1;" : "=f"(r) : "f"(x)); return r;
}
__device__ __forceinline__ float rcpf_(float x) {
    float r; asm("rcp.approx.f32 %0, %1;" : "=f"(r) : "f"(x)); return r;
}

// silu on both packed lanes
__device__ __forceinline__ ull silu2u(ull x) {
    const float NL2E = -1.4426950408889634f;
    float lo, hi; unpackf2(x, lo, hi);
    float e0 = ex2f(NL2E * lo);
    float e1 = ex2f(NL2E * hi);
    float r0 = rcpf_(1.0f + e0);
    float r1 = rcpf_(1.0f + e1);
    return packf2(lo * r0, hi * r1);
}

// One 32->32 layer + SiLU for two doses. Weights row-major [i][j] in smem.
__device__ __forceinline__ void mlp_layer(unsigned wbase,
                                          const float2* __restrict__ Bp,
                                          const ull* __restrict__ hA,
                                          const ull* __restrict__ hB,
                                          ull* __restrict__ oA,
                                          ull* __restrict__ oB) {
    ull accA[16], accB[16];
#pragma unroll
    for (int jp = 0; jp < 16; jp++) {
        float2 b = Bp[jp];
        ull bb = packf2(b.x, b.y);
        accA[jp] = bb; accB[jp] = bb;
    }
#pragma unroll
    for (int k = 0; k < 16; k++) {
        float a0, a1, b0, b1;
        unpackf2(hA[k], a0, a1);
        unpackf2(hB[k], b0, b1);
        // i = 2k
        {
            ull dA = dupf(a0), dB = dupf(b0);
            unsigned rb = wbase + (2 * k) * 128;
#pragma unroll
            for (int jp = 0; jp < 16; jp += 2) {
                ull w0, w1;
                asm("ld.shared.v2.u64 {%0, %1}, [%2];"
                    : "=l"(w0), "=l"(w1) : "r"(rb + jp * 8));
                accA[jp]     = fma2u(dA, w0, accA[jp]);
                accA[jp + 1] = fma2u(dA, w1, accA[jp + 1]);
                accB[jp]     = fma2u(dB, w0, accB[jp]);
                accB[jp + 1] = fma2u(dB, w1, accB[jp + 1]);
            }
        }
        // i = 2k+1
        {
            ull dA = dupf(a1), dB = dupf(b1);
            unsigned rb = wbase + (2 * k + 1) * 128;
#pragma unroll
            for (int jp = 0; jp < 16; jp += 2) {
                ull w0, w1;
                asm("ld.shared.v2.u64 {%0, %1}, [%2];"
                    : "=l"(w0), "=l"(w1) : "r"(rb + jp * 8));
                accA[jp]     = fma2u(dA, w0, accA[jp]);
                accA[jp + 1] = fma2u(dA, w1, accA[jp + 1]);
                accB[jp]     = fma2u(dB, w0, accB[jp]);
                accB[jp + 1] = fma2u(dB, w1, accB[jp + 1]);
            }
        }
    }
#pragma unroll
    for (int jp = 0; jp < 16; jp++) {
        oA[jp] = silu2u(accA[jp]);
        oB[jp] = silu2u(accB[jp]);
    }
}

__global__ void __launch_bounds__(TPB, 3)
dose_encoder_kernel(const float* __restrict__ t_abs,
                    const float* __restrict__ dose_t,
                    const float* __restrict__ amts,
                    const float* __restrict__ ss,
                    const float* __restrict__ ii,
                    const float* __restrict__ span_p,
                    const float* __restrict__ logsig,
                    const float* __restrict__ W1,
                    const float* __restrict__ b1,
                    const float* __restrict__ W2,
                    const float* __restrict__ b2,
                    const float* __restrict__ W3,
                    const float* __restrict__ b3,
                    const float* __restrict__ W4,
                    const float* __restrict__ b4,
                    float* __restrict__ out,
                    int T) {
    __shared__ Smem S;
    const int tid  = threadIdx.x;
    const int lane = tid & 31;
    const int warp = tid >> 5;

    const float span  = span_p[0];
    const float sigma = expf(logsig[0]);
    const float wc_l2 = -0.5f / (sigma * sigma) * 1.4426950408889634f;

    // ---- prolog: stage weights (row-major, no duplication) ----
    {
        const float4* w2g = (const float4*)W2;
        const float4* w3g = (const float4*)W3;
        float4* w2s = (float4*)S.W2s;
        float4* w3s = (float4*)S.W3s;
        for (int i = tid; i < 256; i += TPB) { w2s[i] = w2g[i]; w3s[i] = w3g[i]; }
    }
    if (tid < 16) {
        S.B2p[tid] = make_float2(b2[2 * tid], b2[2 * tid + 1]);
        S.B3p[tid] = make_float2(b3[2 * tid], b3[2 * tid + 1]);
        S.W4p[tid] = make_float2(W4[2 * tid], W4[2 * tid + 1]);
    }
    if (tid < 32) { S.W1t[tid] = W1[tid]; S.W1dl[tid] = W1[64 + tid]; }

    // ---- per-thread dose pair V vectors ----
    const int d0 = 2 * tid, d1 = d0 + 1;
    const float dn0 = dose_t[d0] / span;
    const float dn1 = dose_t[d1] / span;
    {
        float la0 = log1pf(amts[d0]), la1 = log1pf(amts[d1]);
        float spe = span + 1e-6f;
        float ssn0 = ss[d0] / spe, ssn1 = ss[d1] / spe;
        float iin0 = ii[d0] / spe, iin1 = ii[d1] / spe;
        for (int jp = 0; jp < 16; jp++) {
            int j0 = 2 * jp, j1 = j0 + 1;
            float w_dt0 = W1[j0],       w_dt1 = W1[j1];
            float w_la0 = W1[32 + j0],  w_la1 = W1[32 + j1];
            float w_ss0 = W1[96 + j0],  w_ss1 = W1[96 + j1];
            float w_ii0 = W1[128 + j0], w_ii1 = W1[128 + j1];
            float bb0 = b1[j0], bb1 = b1[j1];
            float4 o;
            o.x = fmaf(-dn0, w_dt0, fmaf(la0, w_la0, fmaf(ssn0, w_ss0, fmaf(iin0, w_ii0, bb0))));
            o.y = fmaf(-dn0, w_dt1, fmaf(la0, w_la1, fmaf(ssn0, w_ss1, fmaf(iin0, w_ii1, bb1))));
            o.z = fmaf(-dn1, w_dt0, fmaf(la1, w_la0, fmaf(ssn1, w_ss0, fmaf(iin1, w_ii0, bb0))));
            o.w = fmaf(-dn1, w_dt1, fmaf(la1, w_la1, fmaf(ssn1, w_ss1, fmaf(iin1, w_ii1, bb1))));
            S.V4[jp][tid] = o;
        }
    }
    __syncthreads();

    const float INFP = __int_as_float(0x7f800000);
    const float b4v  = b4[0];
    const unsigned w2base = (unsigned)__cvta_generic_to_shared(S.W2s);
    const unsigned w3base = (unsigned)__cvta_generic_to_shared(S.W3s);

    const int t0 = blockIdx.x * G_T;
#pragma unroll 1
    for (int g = 0; g < G_T; g++) {
        int tt = t0 + g;
        if (tt >= T) break;
        float tnorm = t_abs[tt] / span;
        float dtA = tnorm - dn0;
        float dtB = tnorm - dn1;

        // dt_last = block-wide min over valid doses
        float m = fminf(dtA >= 0.0f ? dtA : INFP, dtB >= 0.0f ? dtB : INFP);
#pragma unroll
        for (int off = 16; off > 0; off >>= 1)
            m = fminf(m, __shfl_xor_sync(0xffffffffu, m, off));
        if (lane == 0) S.redMin[warp] = m;
        __syncthreads();
        float dtlast = fminf(fminf(S.redMin[0], S.redMin[1]),
                             fminf(S.redMin[2], S.redMin[3]));
        if (tid < 16) {
            int j0 = 2 * tid;
            float u0 = fmaf(tnorm, S.W1t[j0],     dtlast * S.W1dl[j0]);
            float u1 = fmaf(tnorm, S.W1t[j0 + 1], dtlast * S.W1dl[j0 + 1]);
            S.Up[tid] = make_float2(u0, u1);
        }
        __syncthreads();

        // ---- layer 1: adds + SiLU ----
        ull hA[16], hB[16], h2A[16], h2B[16];
#pragma unroll
        for (int jp = 0; jp < 16; jp++) {
            float4 v = S.V4[jp][tid];
            float2 u = S.Up[jp];
            hA[jp] = silu2u(packf2(u.x + v.x, u.y + v.y));
            hB[jp] = silu2u(packf2(u.x + v.z, u.y + v.w));
        }

        // ---- layers 2, 3 ----
        mlp_layer(w2base, S.B2p, hA, hB, h2A, h2B);
        mlp_layer(w3base, S.B3p, h2A, h2B, hA, hB);

        // ---- layer 4 ----
        ull sA = packf2(0.0f, 0.0f), sB = sA;
#pragma unroll
        for (int jp = 0; jp < 16; jp++) {
            float2 w4 = S.W4p[jp];
            ull wp = packf2(w4.x, w4.y);
            sA = fma2u(hA[jp], wp, sA);
            sB = fma2u(hB[jp], wp, sB);
        }
        float sa0, sa1, sb0, sb1;
        unpackf2(sA, sa0, sa1);
        unpackf2(sB, sb0, sb1);
        float scoreA = sa0 + sa1 + b4v;
        float scoreB = sb0 + sb1 + b4v;

        // ---- gaussian weight + masked accumulate ----
        float wA = (dtA >= 0.0f) ? ex2f(wc_l2 * dtA * dtA) : 0.0f;
        float wB = (dtB >= 0.0f) ? ex2f(wc_l2 * dtB * dtB) : 0.0f;
        float part = scoreA * wA + scoreB * wB;
#pragma unroll
        for (int off = 16; off > 0; off >>= 1)
            part += __shfl_xor_sync(0xffffffffu, part, off);
        if (lane == 0) S.redSum[warp] = part;
        __syncthreads();
        if (tid == 0)
            out[tt] = (S.redSum[0] + S.redSum[1]) + (S.redSum[2] + S.redSum[3]);
    }
}

extern "C" void kernel_launch(void* const* d_in, const int* in_sizes, int n_in,
                              void* d_out, int out_size) {
    const float* t_abs  = (const float*)d_in[0];
    const float* dose_t = (const float*)d_in[1];
    const float* amts   = (const float*)d_in[2];
    const float* ss     = (const float*)d_in[3];
    const float* ii     = (const float*)d_in[4];
    const float* span_p = (const float*)d_in[5];
    const float* logsig = (const float*)d_in[6];
    const float* W1     = (const float*)d_in[7];
    const float* b1     = (const float*)d_in[8];
    const float* W2     = (const float*)d_in[9];
    const float* b2     = (const float*)d_in[10];
    const float* W3     = (const float*)d_in[11];
    const float* b3     = (const float*)d_in[12];
    const float* W4     = (const float*)d_in[13];
    const float* b4     = (const float*)d_in[14];
    float* out = (float*)d_out;
    const int T = in_sizes[0];

    int grid = (T + G_T - 1) / G_T;
    dose_encoder_kernel<<<grid, TPB>>>(
        t_abs, dose_t, amts, ss, ii, span_p, logsig,
        W1, b1, W2, b2, W3, b3, W4, b4, out, T);
}

// round 9
// speedup vs baseline: 1.6955x; 1.6849x over previous
#include <cuda_runtime.h>
#include <cstdint>

// ---------------------------------------------------------------------------
// DoseEncoder — warp-autonomous j-packed f32x2 formulation.
//
//  * 3-kernel pipeline (all graph-capturable, no allocs):
//      1) dtlast_kernel : binary search over sorted doses -> g_dtlast[t]
//      2) main kernel   : grid (T/64, 4). Block = 64 t x 64 doses.
//                         Warp w owns t's [tile+16w, tile+16w+16): NO
//                         __syncthreads in the main loop, warps drift freely.
//                         Partial dose-sums stored to g_part[q][t] (STG,
//                         deterministic — no atomics).
//      3) combine_kernel: out[t] = (p0+p1)+(p2+p3)
//  * f32x2 lanes = (hidden j, j+1); 2 doses per thread; weight operand
//    {w[i][j], w[i][j+1]} loaded non-duplicated via ld.shared.v2.u64.
//  * SiLU(x) = y + y*tanh(y), y = x/2  (1 MUFU.TANH per lane).
// ---------------------------------------------------------------------------

#define TPB   128
#define G_T   16          // t per warp
#define T_MAX 32768

typedef unsigned long long ull;

__device__ float g_dtlast[T_MAX];
__device__ float g_part[4 * T_MAX];

struct __align__(16) Smem {
    float4 V4[16][32];    // [jp][lane] = {vA_2jp, vA_2jp+1, vB_2jp, vB_2jp+1} (8 KB)
    float  W2s[32 * 32];  // row-major [i][j]  (4 KB)
    float  W3s[32 * 32];  // (4 KB)
    float2 B2p[16];
    float2 B3p[16];
    float2 W4p[16];
    float2 W1tp[16];      // {W1[0][2j], W1[0][2j+1]}   (tnorm feature row)
    float2 W1dlp[16];     // {W1[2][2j], W1[2][2j+1]}   (dt_last feature row)
};

// ---- packed f32x2 helpers --------------------------------------------------
__device__ __forceinline__ ull packf2(float a, float b) {
    ull r; asm("mov.b64 %0, {%1, %2};" : "=l"(r) : "f"(a), "f"(b)); return r;
}
__device__ __forceinline__ void unpackf2(ull x, float& a, float& b) {
    asm("mov.b64 {%0, %1}, %2;" : "=f"(a), "=f"(b) : "l"(x));
}
__device__ __forceinline__ ull dupf(float a) {
    ull r; asm("mov.b64 %0, {%1, %1};" : "=l"(r) : "f"(a)); return r;
}
__device__ __forceinline__ ull fma2u(ull a, ull b, ull c) {
    ull r; asm("fma.rn.f32x2 %0, %1, %2, %3;" : "=l"(r) : "l"(a), "l"(b), "l"(c));
    return r;
}
__device__ __forceinline__ ull mul2u(ull a, ull b) {
    ull r; asm("mul.rn.f32x2 %0, %1, %2;" : "=l"(r) : "l"(a), "l"(b));
    return r;
}
__device__ __forceinline__ float ex2f(float x) {
    float r; asm("ex2.approx.f32 %0, %1;" : "=f"(r) : "f"(x)); return r;
}
__device__ __forceinline__ float tanhf_(float x) {
    float r; asm("tanh.approx.f32 %0, %1;" : "=f"(r) : "f"(x)); return r;
}

// silu(x) = x*sigmoid(x) = y + y*tanh(y),  y = x/2  — both packed lanes
__device__ __forceinline__ ull silu2u(ull x) {
    ull y = mul2u(x, 0x3F0000003F000000ull);      // {0.5f, 0.5f}
    float y0, y1; unpackf2(y, y0, y1);
    float t0 = tanhf_(y0);
    float t1 = tanhf_(y1);
    return fma2u(y, packf2(t0, t1), y);
}

// One 32->32 layer + SiLU for two doses. Weights row-major [i][j] in smem.
__device__ __forceinline__ void mlp_layer(unsigned wbase,
                                          const float2* __restrict__ Bp,
                                          const ull* __restrict__ hA,
                                          const ull* __restrict__ hB,
                                          ull* __restrict__ oA,
                                          ull* __restrict__ oB) {
    ull accA[16], accB[16];
#pragma unroll
    for (int jp = 0; jp < 16; jp++) {
        float2 b = Bp[jp];
        ull bb = packf2(b.x, b.y);
        accA[jp] = bb; accB[jp] = bb;
    }
#pragma unroll
    for (int k = 0; k < 16; k++) {
        float a0, a1, b0, b1;
        unpackf2(hA[k], a0, a1);
        unpackf2(hB[k], b0, b1);
        {
            ull dA = dupf(a0), dB = dupf(b0);
            unsigned rb = wbase + (2 * k) * 128;
#pragma unroll
            for (int jp = 0; jp < 16; jp += 2) {
                ull w0, w1;
                asm("ld.shared.v2.u64 {%0, %1}, [%2];"
                    : "=l"(w0), "=l"(w1) : "r"(rb + jp * 8));
                accA[jp]     = fma2u(dA, w0, accA[jp]);
                accA[jp + 1] = fma2u(dA, w1, accA[jp + 1]);
                accB[jp]     = fma2u(dB, w0, accB[jp]);
                accB[jp + 1] = fma2u(dB, w1, accB[jp + 1]);
            }
        }
        {
            ull dA = dupf(a1), dB = dupf(b1);
            unsigned rb = wbase + (2 * k + 1) * 128;
#pragma unroll
            for (int jp = 0; jp < 16; jp += 2) {
                ull w0, w1;
                asm("ld.shared.v2.u64 {%0, %1}, [%2];"
                    : "=l"(w0), "=l"(w1) : "r"(rb + jp * 8));
                accA[jp]     = fma2u(dA, w0, accA[jp]);
                accA[jp + 1] = fma2u(dA, w1, accA[jp + 1]);
                accB[jp]     = fma2u(dB, w0, accB[jp]);
                accB[jp + 1] = fma2u(dB, w1, accB[jp + 1]);
            }
        }
    }
#pragma unroll
    for (int jp = 0; jp < 16; jp++) {
        oA[jp] = silu2u(accA[jp]);
        oB[jp] = silu2u(accB[jp]);
    }
}

// ---------------------------------------------------------------------------
// Kernel 1: dt_last via binary search (doses sorted ascending).
// g_dtlast[t] = (t_abs[t] - largest dose <= t_abs[t]) / span, or +inf if none.
// ---------------------------------------------------------------------------
__global__ void dtlast_kernel(const float* __restrict__ t_abs,
                              const float* __restrict__ dose_t,
                              const float* __restrict__ span_p,
                              int T, int D) {
    int i = blockIdx.x * blockDim.x + threadIdx.x;
    if (i >= T) return;
    float ta = t_abs[i];
    float inv_span = 1.0f / span_p[0];
    // pos = number of doses <= ta  (upper bound over sorted array)
    int pos = 0;
#pragma unroll
    for (int s = 256; s > 0; s >>= 1) {
        int np = pos + s;
        if (np <= D && dose_t[np - 1] <= ta) pos = np;
    }
    float dl = (pos > 0) ? (ta - dose_t[pos - 1]) * inv_span
                         : __int_as_float(0x7f800000);
    g_dtlast[i] = dl;
}

// ---------------------------------------------------------------------------
// Kernel 2: main. grid = (ceil(T/64), 4). Block = 64 t x 64 doses.
// ---------------------------------------------------------------------------
__global__ void __launch_bounds__(TPB, 3)
dose_encoder_kernel(const float* __restrict__ t_abs,
                    const float* __restrict__ dose_t,
                    const float* __restrict__ amts,
                    const float* __restrict__ ss,
                    const float* __restrict__ ii,
                    const float* __restrict__ span_p,
                    const float* __restrict__ logsig,
                    const float* __restrict__ W1,
                    const float* __restrict__ b1,
                    const float* __restrict__ W2,
                    const float* __restrict__ b2,
                    const float* __restrict__ W3,
                    const float* __restrict__ b3,
                    const float* __restrict__ W4,
                    const float* __restrict__ b4,
                    int T) {
    __shared__ Smem S;
    const int tid  = threadIdx.x;
    const int lane = tid & 31;
    const int warp = tid >> 5;
    const int q    = blockIdx.y;           // dose quarter
    const int dq0  = q * 64;

    const float span     = span_p[0];
    const float inv_span = 1.0f / span;
    const float sigma    = expf(logsig[0]);
    const float wc_l2    = -0.5f / (sigma * sigma) * 1.4426950408889634f;

    // ---- prolog: stage weights ----
    {
        const float4* w2g = (const float4*)W2;
        const float4* w3g = (const float4*)W3;
        float4* w2s = (float4*)S.W2s;
        float4* w3s = (float4*)S.W3s;
        for (int i = tid; i < 256; i += TPB) { w2s[i] = w2g[i]; w3s[i] = w3g[i]; }
    }
    if (tid < 16) {
        S.B2p[tid]   = make_float2(b2[2 * tid], b2[2 * tid + 1]);
        S.B3p[tid]   = make_float2(b3[2 * tid], b3[2 * tid + 1]);
        S.W4p[tid]   = make_float2(W4[2 * tid], W4[2 * tid + 1]);
        S.W1tp[tid]  = make_float2(W1[2 * tid], W1[2 * tid + 1]);
        S.W1dlp[tid] = make_float2(W1[64 + 2 * tid], W1[64 + 2 * tid + 1]);
    }

    // ---- V vectors for this block's 64 doses (each thread fills 4 jp rows) ----
    {
        int l  = tid & 31;
        int jb = (tid >> 5) * 4;
        int d0 = dq0 + 2 * l, d1 = d0 + 1;
        float dn0 = dose_t[d0] * inv_span;
        float dn1 = dose_t[d1] * inv_span;
        float la0 = log1pf(amts[d0]), la1 = log1pf(amts[d1]);
        float spe = 1.0f / (span + 1e-6f);
        float ssn0 = ss[d0] * spe, ssn1 = ss[d1] * spe;
        float iin0 = ii[d0] * spe, iin1 = ii[d1] * spe;
        for (int jp = jb; jp < jb + 4; jp++) {
            int j0 = 2 * jp, j1 = j0 + 1;
            float w_dt0 = W1[j0],       w_dt1 = W1[j1];
            float w_la0 = W1[32 + j0],  w_la1 = W1[32 + j1];
            float w_ss0 = W1[96 + j0],  w_ss1 = W1[96 + j1];
            float w_ii0 = W1[128 + j0], w_ii1 = W1[128 + j1];
            float bb0 = b1[j0], bb1 = b1[j1];
            float4 o;
            o.x = fmaf(-dn0, w_dt0, fmaf(la0, w_la0, fmaf(ssn0, w_ss0, fmaf(iin0, w_ii0, bb0))));
            o.y = fmaf(-dn0, w_dt1, fmaf(la0, w_la1, fmaf(ssn0, w_ss1, fmaf(iin0, w_ii1, bb1))));
            o.z = fmaf(-dn1, w_dt0, fmaf(la1, w_la0, fmaf(ssn1, w_ss0, fmaf(iin1, w_ii0, bb0))));
            o.w = fmaf(-dn1, w_dt1, fmaf(la1, w_la1, fmaf(ssn1, w_ss1, fmaf(iin1, w_ii1, bb1))));
            S.V4[jp][l] = o;
        }
    }
    __syncthreads();   // the ONLY block barrier

    // per-thread dose constants
    const int d0 = dq0 + 2 * lane, d1 = d0 + 1;
    const float dn0 = dose_t[d0] * inv_span;
    const float dn1 = dose_t[d1] * inv_span;
    const float b4v = b4[0];
    const unsigned w2base = (unsigned)__cvta_generic_to_shared(S.W2s);
    const unsigned w3base = (unsigned)__cvta_generic_to_shared(S.W3s);

    const int tbase = blockIdx.x * (4 * G_T) + warp * G_T;
    float* __restrict__ part_out = g_part + q * T_MAX;

#pragma unroll 1
    for (int g = 0; g < G_T; g++) {
        int tt = tbase + g;
        if (tt >= T) break;
        float tnorm = t_abs[tt] * inv_span;
        float dl    = g_dtlast[tt];
        ull tn2 = dupf(tnorm);
        ull dl2 = dupf(dl);

        // ---- layer 1: pre = tn*W1t + dl*W1dl + V, then SiLU ----
        ull hA[16], hB[16], h2A[16], h2B[16];
#pragma unroll
        for (int jp = 0; jp < 16; jp++) {
            float4 v  = S.V4[jp][lane];
            float2 wt = S.W1tp[jp];
            float2 wd = S.W1dlp[jp];
            ull wtp = packf2(wt.x, wt.y);
            ull wdp = packf2(wd.x, wd.y);
            ull u   = fma2u(tn2, wtp, fma2u(dl2, wdp, packf2(v.x, v.y)));
            ull ub  = fma2u(tn2, wtp, fma2u(dl2, wdp, packf2(v.z, v.w)));
            hA[jp] = silu2u(u);
            hB[jp] = silu2u(ub);
        }

        // ---- layers 2, 3 ----
        mlp_layer(w2base, S.B2p, hA, hB, h2A, h2B);
        mlp_layer(w3base, S.B3p, h2A, h2B, hA, hB);

        // ---- layer 4 ----
        ull sA = packf2(0.0f, 0.0f), sB = sA;
#pragma unroll
        for (int jp = 0; jp < 16; jp++) {
            float2 w4 = S.W4p[jp];
            ull wp = packf2(w4.x, w4.y);
            sA = fma2u(hA[jp], wp, sA);
            sB = fma2u(hB[jp], wp, sB);
        }
        float sa0, sa1, sb0, sb1;
        unpackf2(sA, sa0, sa1);
        unpackf2(sB, sb0, sb1);
        float scoreA = sa0 + sa1 + b4v;
        float scoreB = sb0 + sb1 + b4v;

        // ---- gaussian weight + masked accumulate over this warp's 64 doses ----
        float dtA = tnorm - dn0;
        float dtB = tnorm - dn1;
        float wA = (dtA >= 0.0f) ? ex2f(wc_l2 * dtA * dtA) : 0.0f;
        float wB = (dtB >= 0.0f) ? ex2f(wc_l2 * dtB * dtB) : 0.0f;
        float part = scoreA * wA + scoreB * wB;
#pragma unroll
        for (int off = 16; off > 0; off >>= 1)
            part += __shfl_xor_sync(0xffffffffu, part, off);
        if (lane == 0) part_out[tt] = part;
    }
}

// ---------------------------------------------------------------------------
// Kernel 3: combine quarter partials (deterministic).
// ---------------------------------------------------------------------------
__global__ void combine_kernel(float* __restrict__ out, int T) {
    int i = blockIdx.x * blockDim.x + threadIdx.x;
    if (i >= T) return;
    float p0 = g_part[0 * T_MAX + i];
    float p1 = g_part[1 * T_MAX + i];
    float p2 = g_part[2 * T_MAX + i];
    float p3 = g_part[3 * T_MAX + i];
    out[i] = (p0 + p1) + (p2 + p3);
}

extern "C" void kernel_launch(void* const* d_in, const int* in_sizes, int n_in,
                              void* d_out, int out_size) {
    const float* t_abs  = (const float*)d_in[0];
    const float* dose_t = (const float*)d_in[1];
    const float* amts   = (const float*)d_in[2];
    const float* ss     = (const float*)d_in[3];
    const float* ii     = (const float*)d_in[4];
    const float* span_p = (const float*)d_in[5];
    const float* logsig = (const float*)d_in[6];
    const float* W1     = (const float*)d_in[7];
    const float* b1     = (const float*)d_in[8];
    const float* W2     = (const float*)d_in[9];
    const float* b2     = (const float*)d_in[10];
    const float* W3     = (const float*)d_in[11];
    const float* b3     = (const float*)d_in[12];
    const float* W4     = (const float*)d_in[13];
    const float* b4     = (const float*)d_in[14];
    float* out = (float*)d_out;
    const int T = in_sizes[0];
    const int D = in_sizes[1];

    dtlast_kernel<<<(T + 255) / 256, 256>>>(t_abs, dose_t, span_p, T, D);

    dim3 grid((T + 4 * G_T - 1) / (4 * G_T), 4);
    dose_encoder_kernel<<<grid, TPB>>>(
        t_abs, dose_t, amts, ss, ii, span_p, logsig,
        W1, b1, W2, b2, W3, b3, W4, b4, T);

    combine_kernel<<<(T + 255) / 256, 256>>>(out, T);
}